// round 13
// baseline (speedup 1.0000x reference)
#include <cuda_runtime.h>
#include <cuda_bf16.h>
#include <cstdint>

// ---------------------------------------------------------------------------
// Problem constants
// ---------------------------------------------------------------------------
#define L_SEQ   4096
#define NBATCH  8
#define DM      512                 // d_model (output feature dim, LN dim)
#define MROWS   (L_SEQ * NBATCH)    // 32768
#define KD      512                 // K per GEMM half
#define FD      1024                // W inner dim (2*D)

// ---------------------------------------------------------------------------
// GEMM tile config
// ---------------------------------------------------------------------------
#define BM 64
#define BN 256
#define BK 32
#define A_ROW 40                    // bf16 per A smem row (32 + pad -> 80B, conflict-free ldmatrix)
#define W_ROW 264                   // bf16 per W smem row (256 + pad -> 528B, conflict-free ldmatrix)
#define STG_A  (BM * A_ROW * 2)     // 5120 B
#define STG_W  (BK * W_ROW * 2)     // 16896 B
#define STAGE_BYTES (2 * STG_A + 2 * STG_W)   // 44032
#define SMEM_BYTES  (2 * STAGE_BYTES)         // 88064 (double buffered)
#define NCHUNK (KD / BK)            // 16

#define XBLOCKS (MROWS / BM)        // 512
#define PBLOCKS (L_SEQ / BM)        // 64

// ---------------------------------------------------------------------------
// Device scratch (static allocation only -- no cudaMalloc allowed)
// ---------------------------------------------------------------------------
__device__ __align__(16) __nv_bfloat16 g_W1hi[KD * DM];   // W[:, :512]  k-major
__device__ __align__(16) __nv_bfloat16 g_W1lo[KD * DM];
__device__ __align__(16) __nv_bfloat16 g_W2hi[KD * DM];   // W[:, 512:]  k-major
__device__ __align__(16) __nv_bfloat16 g_W2lo[KD * DM];
__device__ __align__(16) float g_G[(size_t)MROWS * DM];   // x @ W1^T
__device__ __align__(16) float g_P[(size_t)L_SEQ * DM];   // pe @ W2^T

// ---------------------------------------------------------------------------
// PTX helpers
// ---------------------------------------------------------------------------
__device__ __forceinline__ uint32_t smem_u32(const void* p) {
    return (uint32_t)__cvta_generic_to_shared(p);
}

__device__ __forceinline__ void ldm_x4(uint32_t* r, uint32_t addr) {
    asm volatile("ldmatrix.sync.aligned.m8n8.x4.shared.b16 {%0,%1,%2,%3}, [%4];"
                 : "=r"(r[0]), "=r"(r[1]), "=r"(r[2]), "=r"(r[3]) : "r"(addr));
}
__device__ __forceinline__ void ldm_x4_t(uint32_t* r, uint32_t addr) {
    asm volatile("ldmatrix.sync.aligned.m8n8.x4.trans.shared.b16 {%0,%1,%2,%3}, [%4];"
                 : "=r"(r[0]), "=r"(r[1]), "=r"(r[2]), "=r"(r[3]) : "r"(addr));
}
__device__ __forceinline__ void mma16816(float* c, const uint32_t* a, uint32_t b0, uint32_t b1) {
    asm volatile(
        "mma.sync.aligned.m16n8k16.row.col.f32.bf16.bf16.f32 "
        "{%0,%1,%2,%3},{%4,%5,%6,%7},{%8,%9},{%0,%1,%2,%3};"
        : "+f"(c[0]), "+f"(c[1]), "+f"(c[2]), "+f"(c[3])
        : "r"(a[0]), "r"(a[1]), "r"(a[2]), "r"(a[3]), "r"(b0), "r"(b1));
}
__device__ __forceinline__ void cpasync16(uint32_t dst, const void* src) {
    asm volatile("cp.async.cg.shared.global [%0], [%1], 16;" :: "r"(dst), "l"(src));
}
__device__ __forceinline__ void cp_commit() { asm volatile("cp.async.commit_group;"); }
__device__ __forceinline__ void cp_wait0()  { asm volatile("cp.async.wait_group 0;"); }

// split a,b into packed bf16 hi pair and lo pair (memory order: a then b)
__device__ __forceinline__ void split_pack(float a, float b, uint32_t& hi, uint32_t& lo) {
    __nv_bfloat16 ha = __float2bfloat16(a);
    __nv_bfloat16 hb = __float2bfloat16(b);
    __nv_bfloat16 la = __float2bfloat16(a - __bfloat162float(ha));
    __nv_bfloat16 lb = __float2bfloat16(b - __bfloat162float(hb));
    hi = (uint32_t)__bfloat16_as_ushort(ha) | ((uint32_t)__bfloat16_as_ushort(hb) << 16);
    lo = (uint32_t)__bfloat16_as_ushort(la) | ((uint32_t)__bfloat16_as_ushort(lb) << 16);
}

// ---------------------------------------------------------------------------
// Kernel 1: transpose + bf16-split W (d,f row-major -> [f][d] k-major hi/lo)
// ---------------------------------------------------------------------------
__global__ void __launch_bounds__(1024) prep_w_kernel(const float* __restrict__ W) {
    __shared__ float tile[32][33];
    const int tx = threadIdx.x, ty = threadIdx.y;
    const int f0 = blockIdx.x * 32;     // f in [0,1024)
    const int d0 = blockIdx.y * 32;     // d in [0,512)
    tile[ty][tx] = W[(size_t)(d0 + ty) * FD + (f0 + tx)];
    __syncthreads();
    const float v = tile[tx][ty];       // = W[d0+tx][f0+ty]
    const int f = f0 + ty;
    const int d = d0 + tx;
    __nv_bfloat16 hi = __float2bfloat16(v);
    __nv_bfloat16 lo = __float2bfloat16(v - __bfloat162float(hi));
    if (f < KD) {
        g_W1hi[f * DM + d] = hi;
        g_W1lo[f * DM + d] = lo;
    } else {
        g_W2hi[(f - KD) * DM + d] = hi;
        g_W2lo[(f - KD) * DM + d] = lo;
    }
}

// ---------------------------------------------------------------------------
// Kernel 2: C[M,512] = A[M,512] @ Wt^T  with 3-pass bf16 split (fp32-accurate)
//   Single launch covers BOTH the x-GEMM and the pe-GEMM:
//   blockIdx.x <  XBLOCKS : G = x  @ W1^T
//   blockIdx.x >= XBLOCKS : P = pe @ W2^T
// ---------------------------------------------------------------------------
__device__ __forceinline__ void store_a_tile(char* sb, int arow, int ac4,
                                             float4 v0, float4 v1) {
    uint32_t h0, l0, h1, l1, h2, l2, h3, l3;
    split_pack(v0.x, v0.y, h0, l0);
    split_pack(v0.z, v0.w, h1, l1);
    split_pack(v1.x, v1.y, h2, l2);
    split_pack(v1.z, v1.w, h3, l3);
    const int off0 = (arow * A_ROW + ac4 * 4) * 2;
    const int off1 = ((arow + 32) * A_ROW + ac4 * 4) * 2;
    *(uint2*)(sb + off0)          = make_uint2(h0, h1);
    *(uint2*)(sb + STG_A + off0)  = make_uint2(l0, l1);
    *(uint2*)(sb + off1)          = make_uint2(h2, h3);
    *(uint2*)(sb + STG_A + off1)  = make_uint2(l2, l3);
}

__device__ __forceinline__ void cpasync_w_tile(char* sb, const __nv_bfloat16* Whi,
                                               const __nv_bfloat16* Wlo,
                                               int k0, int n0, int tid) {
    uint32_t dhi = smem_u32(sb + 2 * STG_A);
    uint32_t dlo = dhi + STG_W;
#pragma unroll
    for (int i = 0; i < 4; ++i) {
        const int id  = tid + i * 256;      // 0..1023
        const int row = id >> 5;            // 0..31  (k within chunk)
        const int c16 = id & 31;            // 16B column chunk (8 bf16)
        const uint32_t doff = (uint32_t)(row * (W_ROW * 2) + c16 * 16);
        const __nv_bfloat16* sh = Whi + (size_t)(k0 + row) * DM + n0 + c16 * 8;
        const __nv_bfloat16* sl = Wlo + (size_t)(k0 + row) * DM + n0 + c16 * 8;
        cpasync16(dhi + doff, sh);
        cpasync16(dlo + doff, sl);
    }
}

__global__ void __launch_bounds__(256) gemm_split3_kernel(
    const float* __restrict__ Ax,
    const float* __restrict__ Ape,
    float* __restrict__ Cg,
    float* __restrict__ Cp) {
    extern __shared__ char smem[];
    const int tid    = threadIdx.x;
    const int lane   = tid & 31;
    const int wid    = tid >> 5;
    const int warp_m = wid & 1;    // 0..1
    const int warp_n = wid >> 1;   // 0..3

    // -- partition the grid between the two GEMMs --
    const float* A;
    const __nv_bfloat16* Whi;
    const __nv_bfloat16* Wlo;
    float* C;
    int m0;
    if (blockIdx.x < XBLOCKS) {
        A = Ax;  Whi = g_W1hi; Wlo = g_W1lo; C = Cg;
        m0 = blockIdx.x * BM;
    } else {
        A = Ape; Whi = g_W2hi; Wlo = g_W2lo; C = Cp;
        m0 = (blockIdx.x - XBLOCKS) * BM;
    }
    const int n0 = blockIdx.y * BN;

    // A global-load mapping: 64 rows x 8 float4 cols; 2 float4 per thread
    const int arow = tid >> 3;     // 0..31
    const int ac4  = tid & 7;      // 0..7
    const float* aP0 = A + (size_t)(m0 + arow) * KD + ac4 * 4;
    const float* aP1 = aP0 + (size_t)32 * KD;

    float acc[2][8][4];
#pragma unroll
    for (int i = 0; i < 2; ++i)
#pragma unroll
        for (int j = 0; j < 8; ++j)
#pragma unroll
            for (int k = 0; k < 4; ++k) acc[i][j][k] = 0.f;

    // prologue: chunk 0
    {
        float4 v0 = *(const float4*)(aP0);
        float4 v1 = *(const float4*)(aP1);
        store_a_tile(smem, arow, ac4, v0, v1);
        cpasync_w_tile(smem, Whi, Wlo, 0, n0, tid);
        cp_commit();
    }

    // per-lane ldmatrix address components (constant across chunks)
    const int a_r  = (lane & 7) + ((lane >> 3) & 1) * 8;  // row within 16-tile
    const int a_k8 = (lane >> 4) * 8;                     // 8-elem k chunk
    const int w_k  = (lane & 7) + ((lane >> 3) & 1) * 8;  // k row within 16
    const int w_n8 = (lane >> 4) * 8;                     // 8-elem n chunk

    for (int ch = 0; ch < NCHUNK; ++ch) {
        const int cur  = ch & 1;
        const bool more = (ch + 1) < NCHUNK;
        float4 na0, na1;
        if (more) {
            na0 = *(const float4*)(aP0 + (ch + 1) * BK);
            na1 = *(const float4*)(aP1 + (ch + 1) * BK);
        }
        cp_wait0();
        __syncthreads();
        if (more) {
            cpasync_w_tile(smem + (cur ^ 1) * STAGE_BYTES, Whi, Wlo,
                           (ch + 1) * BK, n0, tid);
            cp_commit();
        }
        // ---- compute on stage `cur` ----
        char* sb = smem + cur * STAGE_BYTES;
        const uint32_t sAhi = smem_u32(sb);
        const uint32_t sAlo = sAhi + STG_A;
        const uint32_t sWhi = sAlo + STG_A;
        const uint32_t sWlo = sWhi + STG_W;
#pragma unroll
        for (int ks = 0; ks < 2; ++ks) {
            uint32_t ahi[2][4], alo[2][4], wfr[4][4];
#pragma unroll
            for (int mt = 0; mt < 2; ++mt) {
                const int row  = warp_m * 32 + mt * 16 + a_r;
                const int koff = ks * 16 + a_k8;
                const uint32_t off = (uint32_t)(row * A_ROW + koff) * 2;
                ldm_x4(ahi[mt], sAhi + off);
                ldm_x4(alo[mt], sAlo + off);
            }
            const int krow = ks * 16 + w_k;
            // ---- pass A: load Whi frags (kept in regs), mma ahi x Whi ----
            // All 16 accumulators touched exactly once per pass: same-acc
            // RAW reuse distance = 16 mma (vs 2 before) -> no scoreboard
            // serialization on the HMMA accumulator chain.
#pragma unroll
            for (int nt2 = 0; nt2 < 4; ++nt2) {
                const int ncol = warp_n * 64 + nt2 * 16 + w_n8;
                ldm_x4_t(wfr[nt2], sWhi + (uint32_t)(krow * W_ROW + ncol) * 2);
#pragma unroll
                for (int mt = 0; mt < 2; ++mt) {
                    mma16816(acc[mt][nt2 * 2],     ahi[mt], wfr[nt2][0], wfr[nt2][1]);
                    mma16816(acc[mt][nt2 * 2 + 1], ahi[mt], wfr[nt2][2], wfr[nt2][3]);
                }
            }
            // ---- pass B: mma alo x Whi (regs) ----
#pragma unroll
            for (int nt2 = 0; nt2 < 4; ++nt2) {
#pragma unroll
                for (int mt = 0; mt < 2; ++mt) {
                    mma16816(acc[mt][nt2 * 2],     alo[mt], wfr[nt2][0], wfr[nt2][1]);
                    mma16816(acc[mt][nt2 * 2 + 1], alo[mt], wfr[nt2][2], wfr[nt2][3]);
                }
            }
            // ---- pass C: load Wlo frags, mma ahi x Wlo ----
#pragma unroll
            for (int nt2 = 0; nt2 < 4; ++nt2) {
                const int ncol = warp_n * 64 + nt2 * 16 + w_n8;
                ldm_x4_t(wfr[nt2], sWlo + (uint32_t)(krow * W_ROW + ncol) * 2);
#pragma unroll
                for (int mt = 0; mt < 2; ++mt) {
                    mma16816(acc[mt][nt2 * 2],     ahi[mt], wfr[nt2][0], wfr[nt2][1]);
                    mma16816(acc[mt][nt2 * 2 + 1], ahi[mt], wfr[nt2][2], wfr[nt2][3]);
                }
            }
        }
        if (more) {
            store_a_tile(smem + (cur ^ 1) * STAGE_BYTES, arow, ac4, na0, na1);
        }
    }

    // ---- epilogue: write fp32 tile ----
#pragma unroll
    for (int mt = 0; mt < 2; ++mt) {
        const int r0 = m0 + warp_m * 32 + mt * 16 + (lane >> 2);
#pragma unroll
        for (int n8 = 0; n8 < 8; ++n8) {
            const int cb = n0 + warp_n * 64 + n8 * 8 + (lane & 3) * 2;
            float2 v0 = make_float2(acc[mt][n8][0], acc[mt][n8][1]);
            float2 v1 = make_float2(acc[mt][n8][2], acc[mt][n8][3]);
            *(float2*)(C + (size_t)r0 * DM + cb)       = v0;
            *(float2*)(C + (size_t)(r0 + 8) * DM + cb) = v1;
        }
    }
}

// ---------------------------------------------------------------------------
// nonsat activation: exact root of  y + y^3/3 = z
// y = q^{1/3} - q^{-1/3} with q = 1.5z + sqrt((1.5z)^2+1); v = q^{-1/3} by
// bit-trick seed + 3 division-free Newton steps; 1 fast-div polish.
// MUFU ops: 1 RSQ + 1 RCP.
// ---------------------------------------------------------------------------
__device__ __forceinline__ float nonsat_root(float z) {
    const float s = 1.5f * fabsf(z);
    const float w = fmaf(s, s, 1.0f);
    const float t = w * rsqrtf(w);               // sqrt(w), 1 MUFU
    const float q = s + t;                       // q >= 1
    float v = __int_as_float(0x549E80CE - __float_as_int(q) / 3);
#pragma unroll
    for (int it = 0; it < 3; ++it) {
        const float vv = v * v;
        v = v * fmaf(-q * v, vv, 4.0f) * (1.0f / 3.0f);
    }
    float y = fmaf(q * v, v, -v);                // u - 1/u
    y = copysignf(y, z);
    const float yy = y * y;
    y = __fdividef(fmaf(0.66666666666667f * yy, y, z), yy + 1.0f);
    return y;
}

// ---------------------------------------------------------------------------
// Kernel 3: h = G + P + b ; LayerNorm(gamma,beta) ; nonsat activation
// one warp per row (512 floats)
// ---------------------------------------------------------------------------
__global__ void __launch_bounds__(256) ln_act_kernel(
    const float* __restrict__ bias, const float* __restrict__ gamma,
    const float* __restrict__ beta, float* __restrict__ out) {
    const int row  = (int)((blockIdx.x * 256 + threadIdx.x) >> 5);
    const int lane = threadIdx.x & 31;

    const float4* G4 = (const float4*)(g_G + (size_t)row * DM);
    const float4* P4 = (const float4*)(g_P + (size_t)(row >> 3) * DM);
    const float4* B4 = (const float4*)bias;

    float4 h[4];
    float s = 0.f, sq = 0.f;
#pragma unroll
    for (int j = 0; j < 4; ++j) {
        const int idx = lane + j * 32;
        float4 g = G4[idx], p = P4[idx], bb = B4[idx];
        float4 t;
        t.x = g.x + p.x + bb.x;
        t.y = g.y + p.y + bb.y;
        t.z = g.z + p.z + bb.z;
        t.w = g.w + p.w + bb.w;
        h[j] = t;
        s  += t.x + t.y + t.z + t.w;
        sq += t.x * t.x + t.y * t.y + t.z * t.z + t.w * t.w;
    }
#pragma unroll
    for (int o = 16; o; o >>= 1) {
        s  += __shfl_xor_sync(0xffffffffu, s, o);
        sq += __shfl_xor_sync(0xffffffffu, sq, o);
    }
    const float mu   = s * (1.f / 512.f);
    const float var  = sq * (1.f / 512.f) - mu * mu;
    const float rstd = rsqrtf(var + 1e-5f);

    float4* O4 = (float4*)(out + (size_t)row * DM);
    const float4* Ga4 = (const float4*)gamma;
    const float4* Be4 = (const float4*)beta;
#pragma unroll
    for (int j = 0; j < 4; ++j) {
        const int idx = lane + j * 32;
        float4 ga = Ga4[idx], be = Be4[idx];
        float4 o;
        o.x = nonsat_root(fmaf((h[j].x - mu) * rstd, ga.x, be.x));
        o.y = nonsat_root(fmaf((h[j].y - mu) * rstd, ga.y, be.y));
        o.z = nonsat_root(fmaf((h[j].z - mu) * rstd, ga.z, be.z));
        o.w = nonsat_root(fmaf((h[j].w - mu) * rstd, ga.w, be.w));
        O4[idx] = o;
    }
}

// ---------------------------------------------------------------------------
// Launch
// ---------------------------------------------------------------------------
extern "C" void kernel_launch(void* const* d_in, const int* in_sizes, int n_in,
                              void* d_out, int out_size) {
    (void)in_sizes; (void)n_in; (void)out_size;
    const float* x     = (const float*)d_in[0];   // (4096, 8, 512)
    const float* W     = (const float*)d_in[1];   // (512, 1024)
    const float* b     = (const float*)d_in[2];   // (512,)
    const float* gamma = (const float*)d_in[3];   // (512,)
    const float* beta  = (const float*)d_in[4];   // (512,)
    const float* pe    = (const float*)d_in[5];   // (5000, 512)
    float* out = (float*)d_out;

    cudaFuncSetAttribute(gemm_split3_kernel,
                         cudaFuncAttributeMaxDynamicSharedMemorySize, SMEM_BYTES);

    float *G, *P;
    cudaGetSymbolAddress((void**)&G, g_G);
    cudaGetSymbolAddress((void**)&P, g_P);

    // 1) W transpose + bf16 split
    prep_w_kernel<<<dim3(FD / 32, DM / 32), dim3(32, 32)>>>(W);
    // 2) merged GEMM launch: G = x @ W1^T  and  P = pe @ W2^T
    gemm_split3_kernel<<<dim3(XBLOCKS + PBLOCKS, DM / BN), 256, SMEM_BYTES>>>(x, pe, G, P);
    // 3) bias + LN + low-MUFU nonsat activation
    ln_act_kernel<<<MROWS / 8, 256>>>(b, gamma, beta, out);
}

// round 14
// speedup vs baseline: 1.7302x; 1.7302x over previous
#include <cuda_runtime.h>
#include <cuda_fp16.h>
#include <cstdint>

// ---------------------------------------------------------------------------
// Problem constants
// ---------------------------------------------------------------------------
#define L_SEQ   4096
#define NBATCH  8
#define DM      512                 // d_model (output feature dim, LN dim)
#define MROWS   (L_SEQ * NBATCH)    // 32768
#define KD      512                 // K per GEMM half
#define FD      1024                // W inner dim (2*D)

// ---------------------------------------------------------------------------
// GEMM tile config
// ---------------------------------------------------------------------------
#define BM 64
#define BN 256
#define BK 32
#define A_ROW 40                    // fp16 per A smem row (32 + pad -> 80B, conflict-free ldmatrix)
#define W_ROW 264                   // fp16 per W smem row (256 + pad -> 528B, conflict-free ldmatrix)
#define STG_A  (BM * A_ROW * 2)     // 5120 B
#define STG_W  (BK * W_ROW * 2)     // 16896 B
#define STAGE_BYTES (2 * STG_A + STG_W)       // 27136  [Ahi|Alo|Wh]
#define SMEM_BYTES  (2 * STAGE_BYTES)         // 54272 (double buffered)
#define NCHUNK (KD / BK)            // 16

#define XBLOCKS (MROWS / BM)        // 512
#define PBLOCKS (L_SEQ / BM)        // 64

// ---------------------------------------------------------------------------
// Device scratch (static allocation only -- no cudaMalloc allowed)
// ---------------------------------------------------------------------------
__device__ __align__(16) __half g_W1h[KD * DM];   // W[:, :512]  k-major fp16
__device__ __align__(16) __half g_W2h[KD * DM];   // W[:, 512:]  k-major fp16
__device__ __align__(16) float g_G[(size_t)MROWS * DM];   // x @ W1^T
__device__ __align__(16) float g_P[(size_t)L_SEQ * DM];   // pe @ W2^T

// ---------------------------------------------------------------------------
// PTX helpers
// ---------------------------------------------------------------------------
__device__ __forceinline__ uint32_t smem_u32(const void* p) {
    return (uint32_t)__cvta_generic_to_shared(p);
}

__device__ __forceinline__ void ldm_x4(uint32_t* r, uint32_t addr) {
    asm volatile("ldmatrix.sync.aligned.m8n8.x4.shared.b16 {%0,%1,%2,%3}, [%4];"
                 : "=r"(r[0]), "=r"(r[1]), "=r"(r[2]), "=r"(r[3]) : "r"(addr));
}
__device__ __forceinline__ void ldm_x4_t(uint32_t* r, uint32_t addr) {
    asm volatile("ldmatrix.sync.aligned.m8n8.x4.trans.shared.b16 {%0,%1,%2,%3}, [%4];"
                 : "=r"(r[0]), "=r"(r[1]), "=r"(r[2]), "=r"(r[3]) : "r"(addr));
}
__device__ __forceinline__ void mma16816(float* c, const uint32_t* a, uint32_t b0, uint32_t b1) {
    asm volatile(
        "mma.sync.aligned.m16n8k16.row.col.f32.f16.f16.f32 "
        "{%0,%1,%2,%3},{%4,%5,%6,%7},{%8,%9},{%0,%1,%2,%3};"
        : "+f"(c[0]), "+f"(c[1]), "+f"(c[2]), "+f"(c[3])
        : "r"(a[0]), "r"(a[1]), "r"(a[2]), "r"(a[3]), "r"(b0), "r"(b1));
}
__device__ __forceinline__ void cpasync16(uint32_t dst, const void* src) {
    asm volatile("cp.async.cg.shared.global [%0], [%1], 16;" :: "r"(dst), "l"(src));
}
__device__ __forceinline__ void cp_commit() { asm volatile("cp.async.commit_group;"); }
__device__ __forceinline__ void cp_wait0()  { asm volatile("cp.async.wait_group 0;"); }

// split a,b into packed fp16 hi pair and lo pair (memory order: a then b)
__device__ __forceinline__ void split_pack(float a, float b, uint32_t& hi, uint32_t& lo) {
    __half ha = __float2half_rn(a);
    __half hb = __float2half_rn(b);
    __half la = __float2half_rn(a - __half2float(ha));
    __half lb = __float2half_rn(b - __half2float(hb));
    hi = (uint32_t)__half_as_ushort(ha) | ((uint32_t)__half_as_ushort(hb) << 16);
    lo = (uint32_t)__half_as_ushort(la) | ((uint32_t)__half_as_ushort(lb) << 16);
}

// ---------------------------------------------------------------------------
// Kernel 1: transpose + fp16 W (d,f row-major -> [f][d] k-major)
// ---------------------------------------------------------------------------
__global__ void __launch_bounds__(1024) prep_w_kernel(const float* __restrict__ W) {
    __shared__ float tile[32][33];
    const int tx = threadIdx.x, ty = threadIdx.y;
    const int f0 = blockIdx.x * 32;     // f in [0,1024)
    const int d0 = blockIdx.y * 32;     // d in [0,512)
    tile[ty][tx] = W[(size_t)(d0 + ty) * FD + (f0 + tx)];
    __syncthreads();
    const float v = tile[tx][ty];       // = W[d0+tx][f0+ty]
    const int f = f0 + ty;
    const int d = d0 + tx;
    const __half h = __float2half_rn(v);
    if (f < KD) {
        g_W1h[f * DM + d] = h;
    } else {
        g_W2h[(f - KD) * DM + d] = h;
    }
}

// ---------------------------------------------------------------------------
// Kernel 2: C[M,512] = A[M,512] @ Wt^T  fp16 2-pass A-split (W single fp16)
//   Single launch covers BOTH the x-GEMM and the pe-GEMM:
//   blockIdx.x <  XBLOCKS : G = x  @ W1^T
//   blockIdx.x >= XBLOCKS : P = pe @ W2^T
// ---------------------------------------------------------------------------
__device__ __forceinline__ void store_a_tile(char* sb, int arow, int ac4,
                                             float4 v0, float4 v1) {
    uint32_t h0, l0, h1, l1, h2, l2, h3, l3;
    split_pack(v0.x, v0.y, h0, l0);
    split_pack(v0.z, v0.w, h1, l1);
    split_pack(v1.x, v1.y, h2, l2);
    split_pack(v1.z, v1.w, h3, l3);
    const int off0 = (arow * A_ROW + ac4 * 4) * 2;
    const int off1 = ((arow + 32) * A_ROW + ac4 * 4) * 2;
    *(uint2*)(sb + off0)          = make_uint2(h0, h1);
    *(uint2*)(sb + STG_A + off0)  = make_uint2(l0, l1);
    *(uint2*)(sb + off1)          = make_uint2(h2, h3);
    *(uint2*)(sb + STG_A + off1)  = make_uint2(l2, l3);
}

__device__ __forceinline__ void cpasync_w_tile(char* sb, const __half* Wh,
                                               int k0, int n0, int tid) {
    uint32_t dh = smem_u32(sb + 2 * STG_A);
#pragma unroll
    for (int i = 0; i < 4; ++i) {
        const int id  = tid + i * 256;      // 0..1023
        const int row = id >> 5;            // 0..31  (k within chunk)
        const int c16 = id & 31;            // 16B column chunk (8 fp16)
        const uint32_t doff = (uint32_t)(row * (W_ROW * 2) + c16 * 16);
        cpasync16(dh + doff, Wh + (size_t)(k0 + row) * DM + n0 + c16 * 8);
    }
}

__global__ void __launch_bounds__(256) gemm_split2_kernel(
    const float* __restrict__ Ax,
    const float* __restrict__ Ape,
    float* __restrict__ Cg,
    float* __restrict__ Cp) {
    extern __shared__ char smem[];
    const int tid    = threadIdx.x;
    const int lane   = tid & 31;
    const int wid    = tid >> 5;
    const int warp_m = wid & 1;    // 0..1
    const int warp_n = wid >> 1;   // 0..3

    // -- partition the grid between the two GEMMs --
    const float* A;
    const __half* Wh;
    float* C;
    int m0;
    if (blockIdx.x < XBLOCKS) {
        A = Ax;  Wh = g_W1h; C = Cg;
        m0 = blockIdx.x * BM;
    } else {
        A = Ape; Wh = g_W2h; C = Cp;
        m0 = (blockIdx.x - XBLOCKS) * BM;
    }
    const int n0 = blockIdx.y * BN;

    // A global-load mapping: 64 rows x 8 float4 cols; 2 float4 per thread
    const int arow = tid >> 3;     // 0..31
    const int ac4  = tid & 7;      // 0..7
    const float* aP0 = A + (size_t)(m0 + arow) * KD + ac4 * 4;
    const float* aP1 = aP0 + (size_t)32 * KD;

    float acc[2][8][4];
#pragma unroll
    for (int i = 0; i < 2; ++i)
#pragma unroll
        for (int j = 0; j < 8; ++j)
#pragma unroll
            for (int k = 0; k < 4; ++k) acc[i][j][k] = 0.f;

    // prologue: chunk 0
    {
        float4 v0 = *(const float4*)(aP0);
        float4 v1 = *(const float4*)(aP1);
        store_a_tile(smem, arow, ac4, v0, v1);
        cpasync_w_tile(smem, Wh, 0, n0, tid);
        cp_commit();
    }

    // per-lane ldmatrix address components (constant across chunks)
    const int a_r  = (lane & 7) + ((lane >> 3) & 1) * 8;  // row within 16-tile
    const int a_k8 = (lane >> 4) * 8;                     // 8-elem k chunk
    const int w_k  = (lane & 7) + ((lane >> 3) & 1) * 8;  // k row within 16
    const int w_n8 = (lane >> 4) * 8;                     // 8-elem n chunk

    for (int ch = 0; ch < NCHUNK; ++ch) {
        const int cur  = ch & 1;
        const bool more = (ch + 1) < NCHUNK;
        float4 na0, na1;
        if (more) {
            na0 = *(const float4*)(aP0 + (ch + 1) * BK);
            na1 = *(const float4*)(aP1 + (ch + 1) * BK);
        }
        cp_wait0();
        __syncthreads();
        if (more) {
            cpasync_w_tile(smem + (cur ^ 1) * STAGE_BYTES, Wh,
                           (ch + 1) * BK, n0, tid);
            cp_commit();
        }
        // ---- compute on stage `cur` (R12-proven interleaved ordering) ----
        char* sb = smem + cur * STAGE_BYTES;
        const uint32_t sAhi = smem_u32(sb);
        const uint32_t sAlo = sAhi + STG_A;
        const uint32_t sWh  = sAlo + STG_A;
#pragma unroll
        for (int ks = 0; ks < 2; ++ks) {
            uint32_t ahi[2][4], alo[2][4];
#pragma unroll
            for (int mt = 0; mt < 2; ++mt) {
                const int row  = warp_m * 32 + mt * 16 + a_r;
                const int koff = ks * 16 + a_k8;
                const uint32_t off = (uint32_t)(row * A_ROW + koff) * 2;
                ldm_x4(ahi[mt], sAhi + off);
                ldm_x4(alo[mt], sAlo + off);
            }
#pragma unroll
            for (int nt2 = 0; nt2 < 4; ++nt2) {
                const int krow = ks * 16 + w_k;
                const int ncol = warp_n * 64 + nt2 * 16 + w_n8;
                uint32_t w[4];
                ldm_x4_t(w, sWh + (uint32_t)(krow * W_ROW + ncol) * 2);
#pragma unroll
                for (int mt = 0; mt < 2; ++mt) {
                    mma16816(acc[mt][nt2 * 2],     ahi[mt], w[0], w[1]);
                    mma16816(acc[mt][nt2 * 2 + 1], ahi[mt], w[2], w[3]);
                    mma16816(acc[mt][nt2 * 2],     alo[mt], w[0], w[1]);
                    mma16816(acc[mt][nt2 * 2 + 1], alo[mt], w[2], w[3]);
                }
            }
        }
        if (more) {
            store_a_tile(smem + (cur ^ 1) * STAGE_BYTES, arow, ac4, na0, na1);
        }
    }

    // ---- epilogue: write fp32 tile ----
#pragma unroll
    for (int mt = 0; mt < 2; ++mt) {
        const int r0 = m0 + warp_m * 32 + mt * 16 + (lane >> 2);
#pragma unroll
        for (int n8 = 0; n8 < 8; ++n8) {
            const int cb = n0 + warp_n * 64 + n8 * 8 + (lane & 3) * 2;
            float2 v0 = make_float2(acc[mt][n8][0], acc[mt][n8][1]);
            float2 v1 = make_float2(acc[mt][n8][2], acc[mt][n8][3]);
            *(float2*)(C + (size_t)r0 * DM + cb)       = v0;
            *(float2*)(C + (size_t)(r0 + 8) * DM + cb) = v1;
        }
    }
}

// ---------------------------------------------------------------------------
// nonsat activation: exact root of  y + y^3/3 = z
// y = q^{1/3} - q^{-1/3} with q = 1.5z + sqrt((1.5z)^2+1); v = q^{-1/3} by
// bit-trick seed + 3 division-free Newton steps; 1 fast-div polish.
// MUFU ops: 1 RSQ + 1 RCP.
// ---------------------------------------------------------------------------
__device__ __forceinline__ float nonsat_root(float z) {
    const float s = 1.5f * fabsf(z);
    const float w = fmaf(s, s, 1.0f);
    const float t = w * rsqrtf(w);               // sqrt(w), 1 MUFU
    const float q = s + t;                       // q >= 1
    float v = __int_as_float(0x549E80CE - __float_as_int(q) / 3);
#pragma unroll
    for (int it = 0; it < 3; ++it) {
        const float vv = v * v;
        v = v * fmaf(-q * v, vv, 4.0f) * (1.0f / 3.0f);
    }
    float y = fmaf(q * v, v, -v);                // u - 1/u
    y = copysignf(y, z);
    const float yy = y * y;
    y = __fdividef(fmaf(0.66666666666667f * yy, y, z), yy + 1.0f);
    return y;
}

// ---------------------------------------------------------------------------
// Kernel 3: h = G + P + b ; LayerNorm(gamma,beta) ; nonsat activation
// one warp per row (512 floats)
// ---------------------------------------------------------------------------
__global__ void __launch_bounds__(256) ln_act_kernel(
    const float* __restrict__ bias, const float* __restrict__ gamma,
    const float* __restrict__ beta, float* __restrict__ out) {
    const int row  = (int)((blockIdx.x * 256 + threadIdx.x) >> 5);
    const int lane = threadIdx.x & 31;

    const float4* G4 = (const float4*)(g_G + (size_t)row * DM);
    const float4* P4 = (const float4*)(g_P + (size_t)(row >> 3) * DM);
    const float4* B4 = (const float4*)bias;

    float4 h[4];
    float s = 0.f, sq = 0.f;
#pragma unroll
    for (int j = 0; j < 4; ++j) {
        const int idx = lane + j * 32;
        float4 g = G4[idx], p = P4[idx], bb = B4[idx];
        float4 t;
        t.x = g.x + p.x + bb.x;
        t.y = g.y + p.y + bb.y;
        t.z = g.z + p.z + bb.z;
        t.w = g.w + p.w + bb.w;
        h[j] = t;
        s  += t.x + t.y + t.z + t.w;
        sq += t.x * t.x + t.y * t.y + t.z * t.z + t.w * t.w;
    }
#pragma unroll
    for (int o = 16; o; o >>= 1) {
        s  += __shfl_xor_sync(0xffffffffu, s, o);
        sq += __shfl_xor_sync(0xffffffffu, sq, o);
    }
    const float mu   = s * (1.f / 512.f);
    const float var  = sq * (1.f / 512.f) - mu * mu;
    const float rstd = rsqrtf(var + 1e-5f);

    float4* O4 = (float4*)(out + (size_t)row * DM);
    const float4* Ga4 = (const float4*)gamma;
    const float4* Be4 = (const float4*)beta;
#pragma unroll
    for (int j = 0; j < 4; ++j) {
        const int idx = lane + j * 32;
        float4 ga = Ga4[idx], be = Be4[idx];
        float4 o;
        o.x = nonsat_root(fmaf((h[j].x - mu) * rstd, ga.x, be.x));
        o.y = nonsat_root(fmaf((h[j].y - mu) * rstd, ga.y, be.y));
        o.z = nonsat_root(fmaf((h[j].z - mu) * rstd, ga.z, be.z));
        o.w = nonsat_root(fmaf((h[j].w - mu) * rstd, ga.w, be.w));
        O4[idx] = o;
    }
}

// ---------------------------------------------------------------------------
// Launch
// ---------------------------------------------------------------------------
extern "C" void kernel_launch(void* const* d_in, const int* in_sizes, int n_in,
                              void* d_out, int out_size) {
    (void)in_sizes; (void)n_in; (void)out_size;
    const float* x     = (const float*)d_in[0];   // (4096, 8, 512)
    const float* W     = (const float*)d_in[1];   // (512, 1024)
    const float* b     = (const float*)d_in[2];   // (512,)
    const float* gamma = (const float*)d_in[3];   // (512,)
    const float* beta  = (const float*)d_in[4];   // (512,)
    const float* pe    = (const float*)d_in[5];   // (5000, 512)
    float* out = (float*)d_out;

    cudaFuncSetAttribute(gemm_split2_kernel,
                         cudaFuncAttributeMaxDynamicSharedMemorySize, SMEM_BYTES);

    float *G, *P;
    cudaGetSymbolAddress((void**)&G, g_G);
    cudaGetSymbolAddress((void**)&P, g_P);

    // 1) W transpose + fp16 convert
    prep_w_kernel<<<dim3(FD / 32, DM / 32), dim3(32, 32)>>>(W);
    // 2) merged GEMM launch: G = x @ W1^T  and  P = pe @ W2^T
    gemm_split2_kernel<<<dim3(XBLOCKS + PBLOCKS, DM / BN), 256, SMEM_BYTES>>>(x, pe, G, P);
    // 3) bias + LN + low-MUFU nonsat activation
    ln_act_kernel<<<MROWS / 8, 256>>>(b, gamma, beta, out);
}

// round 15
// speedup vs baseline: 2.0989x; 1.2131x over previous
#include <cuda_runtime.h>
#include <cuda_fp16.h>
#include <cstdint>

// ---------------------------------------------------------------------------
// Problem constants
// ---------------------------------------------------------------------------
#define L_SEQ   4096
#define NBATCH  8
#define DM      512                 // d_model (output feature dim, LN dim)
#define MROWS   (L_SEQ * NBATCH)    // 32768
#define KD      512                 // K per GEMM half
#define FD      1024                // W inner dim (2*D)

// ---------------------------------------------------------------------------
// GEMM tile config
// ---------------------------------------------------------------------------
#define BM 64
#define BN 256
#define BK 32
#define A_ROW 40                    // fp16 per A smem row (32 + pad -> 80B, conflict-free ldmatrix)
#define W_ROW 264                   // fp16 per W smem row (256 + pad -> 528B, conflict-free ldmatrix)
#define STG_A  (BM * A_ROW * 2)     // 5120 B
#define STG_W  (BK * W_ROW * 2)     // 16896 B
#define STAGE_BYTES (STG_A + STG_W)           // 22016  [Ah|Wh]
#define SMEM_BYTES  (2 * STAGE_BYTES)         // 44032 (double buffered)
#define NCHUNK (KD / BK)            // 16

#define XBLOCKS (MROWS / BM)        // 512
#define PBLOCKS (L_SEQ / BM)        // 64

// ---------------------------------------------------------------------------
// Device scratch (static allocation only -- no cudaMalloc allowed)
// ---------------------------------------------------------------------------
__device__ __align__(16) __half g_W1h[KD * DM];   // W[:, :512]  k-major fp16
__device__ __align__(16) __half g_W2h[KD * DM];   // W[:, 512:]  k-major fp16
__device__ __align__(16) float g_G[(size_t)MROWS * DM];   // x @ W1^T
__device__ __align__(16) float g_P[(size_t)L_SEQ * DM];   // pe @ W2^T

// ---------------------------------------------------------------------------
// PTX helpers
// ---------------------------------------------------------------------------
__device__ __forceinline__ uint32_t smem_u32(const void* p) {
    return (uint32_t)__cvta_generic_to_shared(p);
}

__device__ __forceinline__ void ldm_x4(uint32_t* r, uint32_t addr) {
    asm volatile("ldmatrix.sync.aligned.m8n8.x4.shared.b16 {%0,%1,%2,%3}, [%4];"
                 : "=r"(r[0]), "=r"(r[1]), "=r"(r[2]), "=r"(r[3]) : "r"(addr));
}
__device__ __forceinline__ void ldm_x4_t(uint32_t* r, uint32_t addr) {
    asm volatile("ldmatrix.sync.aligned.m8n8.x4.trans.shared.b16 {%0,%1,%2,%3}, [%4];"
                 : "=r"(r[0]), "=r"(r[1]), "=r"(r[2]), "=r"(r[3]) : "r"(addr));
}
__device__ __forceinline__ void mma16816(float* c, const uint32_t* a, uint32_t b0, uint32_t b1) {
    asm volatile(
        "mma.sync.aligned.m16n8k16.row.col.f32.f16.f16.f32 "
        "{%0,%1,%2,%3},{%4,%5,%6,%7},{%8,%9},{%0,%1,%2,%3};"
        : "+f"(c[0]), "+f"(c[1]), "+f"(c[2]), "+f"(c[3])
        : "r"(a[0]), "r"(a[1]), "r"(a[2]), "r"(a[3]), "r"(b0), "r"(b1));
}
__device__ __forceinline__ void cpasync16(uint32_t dst, const void* src) {
    asm volatile("cp.async.cg.shared.global [%0], [%1], 16;" :: "r"(dst), "l"(src));
}
__device__ __forceinline__ void cp_commit() { asm volatile("cp.async.commit_group;"); }
__device__ __forceinline__ void cp_wait0()  { asm volatile("cp.async.wait_group 0;"); }

// pack a,b fp32 -> packed fp16 pair
__device__ __forceinline__ uint32_t pack_half2(float a, float b) {
    const __half2 h = __floats2half2_rn(a, b);
    return *(const uint32_t*)&h;
}

// ---------------------------------------------------------------------------
// Kernel 1: transpose + fp16 W (d,f row-major -> [f][d] k-major)
// ---------------------------------------------------------------------------
__global__ void __launch_bounds__(1024) prep_w_kernel(const float* __restrict__ W) {
    __shared__ float tile[32][33];
    const int tx = threadIdx.x, ty = threadIdx.y;
    const int f0 = blockIdx.x * 32;     // f in [0,1024)
    const int d0 = blockIdx.y * 32;     // d in [0,512)
    tile[ty][tx] = W[(size_t)(d0 + ty) * FD + (f0 + tx)];
    __syncthreads();
    const float v = tile[tx][ty];       // = W[d0+tx][f0+ty]
    const int f = f0 + ty;
    const int d = d0 + tx;
    const __half h = __float2half_rn(v);
    if (f < KD) {
        g_W1h[f * DM + d] = h;
    } else {
        g_W2h[(f - KD) * DM + d] = h;
    }
}

// ---------------------------------------------------------------------------
// Kernel 2: C[M,512] = A[M,512] @ Wt^T  single-pass fp16 (A and W fp16)
//   Single launch covers BOTH the x-GEMM and the pe-GEMM:
//   blockIdx.x <  XBLOCKS : G = x  @ W1^T
//   blockIdx.x >= XBLOCKS : P = pe @ W2^T
// ---------------------------------------------------------------------------
__device__ __forceinline__ void store_a_tile(char* sb, int arow, int ac4,
                                             float4 v0, float4 v1) {
    const uint32_t h0 = pack_half2(v0.x, v0.y);
    const uint32_t h1 = pack_half2(v0.z, v0.w);
    const uint32_t h2 = pack_half2(v1.x, v1.y);
    const uint32_t h3 = pack_half2(v1.z, v1.w);
    const int off0 = (arow * A_ROW + ac4 * 4) * 2;
    const int off1 = ((arow + 32) * A_ROW + ac4 * 4) * 2;
    *(uint2*)(sb + off0) = make_uint2(h0, h1);
    *(uint2*)(sb + off1) = make_uint2(h2, h3);
}

__device__ __forceinline__ void cpasync_w_tile(char* sb, const __half* Wh,
                                               int k0, int n0, int tid) {
    uint32_t dh = smem_u32(sb + STG_A);
#pragma unroll
    for (int i = 0; i < 4; ++i) {
        const int id  = tid + i * 256;      // 0..1023
        const int row = id >> 5;            // 0..31  (k within chunk)
        const int c16 = id & 31;            // 16B column chunk (8 fp16)
        const uint32_t doff = (uint32_t)(row * (W_ROW * 2) + c16 * 16);
        cpasync16(dh + doff, Wh + (size_t)(k0 + row) * DM + n0 + c16 * 8);
    }
}

__global__ void __launch_bounds__(256) gemm_fp16_kernel(
    const float* __restrict__ Ax,
    const float* __restrict__ Ape,
    float* __restrict__ Cg,
    float* __restrict__ Cp) {
    extern __shared__ char smem[];
    const int tid    = threadIdx.x;
    const int lane   = tid & 31;
    const int wid    = tid >> 5;
    const int warp_m = wid & 1;    // 0..1
    const int warp_n = wid >> 1;   // 0..3

    // -- partition the grid between the two GEMMs --
    const float* A;
    const __half* Wh;
    float* C;
    int m0;
    if (blockIdx.x < XBLOCKS) {
        A = Ax;  Wh = g_W1h; C = Cg;
        m0 = blockIdx.x * BM;
    } else {
        A = Ape; Wh = g_W2h; C = Cp;
        m0 = (blockIdx.x - XBLOCKS) * BM;
    }
    const int n0 = blockIdx.y * BN;

    // A global-load mapping: 64 rows x 8 float4 cols; 2 float4 per thread
    const int arow = tid >> 3;     // 0..31
    const int ac4  = tid & 7;      // 0..7
    const float* aP0 = A + (size_t)(m0 + arow) * KD + ac4 * 4;
    const float* aP1 = aP0 + (size_t)32 * KD;

    float acc[2][8][4];
#pragma unroll
    for (int i = 0; i < 2; ++i)
#pragma unroll
        for (int j = 0; j < 8; ++j)
#pragma unroll
            for (int k = 0; k < 4; ++k) acc[i][j][k] = 0.f;

    // prologue: chunk 0
    {
        float4 v0 = *(const float4*)(aP0);
        float4 v1 = *(const float4*)(aP1);
        store_a_tile(smem, arow, ac4, v0, v1);
        cpasync_w_tile(smem, Wh, 0, n0, tid);
        cp_commit();
    }

    // per-lane ldmatrix address components (constant across chunks)
    const int a_r  = (lane & 7) + ((lane >> 3) & 1) * 8;  // row within 16-tile
    const int a_k8 = (lane >> 4) * 8;                     // 8-elem k chunk
    const int w_k  = (lane & 7) + ((lane >> 3) & 1) * 8;  // k row within 16
    const int w_n8 = (lane >> 4) * 8;                     // 8-elem n chunk

    for (int ch = 0; ch < NCHUNK; ++ch) {
        const int cur  = ch & 1;
        const bool more = (ch + 1) < NCHUNK;
        float4 na0, na1;
        if (more) {
            na0 = *(const float4*)(aP0 + (ch + 1) * BK);
            na1 = *(const float4*)(aP1 + (ch + 1) * BK);
        }
        cp_wait0();
        __syncthreads();
        if (more) {
            cpasync_w_tile(smem + (cur ^ 1) * STAGE_BYTES, Wh,
                           (ch + 1) * BK, n0, tid);
            cp_commit();
        }
        // ---- compute on stage `cur` ----
        char* sb = smem + cur * STAGE_BYTES;
        const uint32_t sAh = smem_u32(sb);
        const uint32_t sWh = sAh + STG_A;
#pragma unroll
        for (int ks = 0; ks < 2; ++ks) {
            uint32_t af[2][4];
#pragma unroll
            for (int mt = 0; mt < 2; ++mt) {
                const int row  = warp_m * 32 + mt * 16 + a_r;
                const int koff = ks * 16 + a_k8;
                ldm_x4(af[mt], sAh + (uint32_t)(row * A_ROW + koff) * 2);
            }
#pragma unroll
            for (int nt2 = 0; nt2 < 4; ++nt2) {
                const int krow = ks * 16 + w_k;
                const int ncol = warp_n * 64 + nt2 * 16 + w_n8;
                uint32_t w[4];
                ldm_x4_t(w, sWh + (uint32_t)(krow * W_ROW + ncol) * 2);
#pragma unroll
                for (int mt = 0; mt < 2; ++mt) {
                    mma16816(acc[mt][nt2 * 2],     af[mt], w[0], w[1]);
                    mma16816(acc[mt][nt2 * 2 + 1], af[mt], w[2], w[3]);
                }
            }
        }
        if (more) {
            store_a_tile(smem + (cur ^ 1) * STAGE_BYTES, arow, ac4, na0, na1);
        }
    }

    // ---- epilogue: write fp32 tile ----
#pragma unroll
    for (int mt = 0; mt < 2; ++mt) {
        const int r0 = m0 + warp_m * 32 + mt * 16 + (lane >> 2);
#pragma unroll
        for (int n8 = 0; n8 < 8; ++n8) {
            const int cb = n0 + warp_n * 64 + n8 * 8 + (lane & 3) * 2;
            float2 v0 = make_float2(acc[mt][n8][0], acc[mt][n8][1]);
            float2 v1 = make_float2(acc[mt][n8][2], acc[mt][n8][3]);
            *(float2*)(C + (size_t)r0 * DM + cb)       = v0;
            *(float2*)(C + (size_t)(r0 + 8) * DM + cb) = v1;
        }
    }
}

// ---------------------------------------------------------------------------
// nonsat activation: exact root of  y + y^3/3 = z
// y = q^{1/3} - q^{-1/3} with q = 1.5z + sqrt((1.5z)^2+1); v = q^{-1/3} by
// bit-trick seed + 3 division-free Newton steps; 1 fast-div polish.
// MUFU ops: 1 RSQ + 1 RCP.
// ---------------------------------------------------------------------------
__device__ __forceinline__ float nonsat_root(float z) {
    const float s = 1.5f * fabsf(z);
    const float w = fmaf(s, s, 1.0f);
    const float t = w * rsqrtf(w);               // sqrt(w), 1 MUFU
    const float q = s + t;                       // q >= 1
    float v = __int_as_float(0x549E80CE - __float_as_int(q) / 3);
#pragma unroll
    for (int it = 0; it < 3; ++it) {
        const float vv = v * v;
        v = v * fmaf(-q * v, vv, 4.0f) * (1.0f / 3.0f);
    }
    float y = fmaf(q * v, v, -v);                // u - 1/u
    y = copysignf(y, z);
    const float yy = y * y;
    y = __fdividef(fmaf(0.66666666666667f * yy, y, z), yy + 1.0f);
    return y;
}

// ---------------------------------------------------------------------------
// Kernel 3: h = G + P + b ; LayerNorm(gamma,beta) ; nonsat activation
// one warp per row (512 floats)
// ---------------------------------------------------------------------------
__global__ void __launch_bounds__(256) ln_act_kernel(
    const float* __restrict__ bias, const float* __restrict__ gamma,
    const float* __restrict__ beta, float* __restrict__ out) {
    const int row  = (int)((blockIdx.x * 256 + threadIdx.x) >> 5);
    const int lane = threadIdx.x & 31;

    const float4* G4 = (const float4*)(g_G + (size_t)row * DM);
    const float4* P4 = (const float4*)(g_P + (size_t)(row >> 3) * DM);
    const float4* B4 = (const float4*)bias;

    float4 h[4];
    float s = 0.f, sq = 0.f;
#pragma unroll
    for (int j = 0; j < 4; ++j) {
        const int idx = lane + j * 32;
        float4 g = G4[idx], p = P4[idx], bb = B4[idx];
        float4 t;
        t.x = g.x + p.x + bb.x;
        t.y = g.y + p.y + bb.y;
        t.z = g.z + p.z + bb.z;
        t.w = g.w + p.w + bb.w;
        h[j] = t;
        s  += t.x + t.y + t.z + t.w;
        sq += t.x * t.x + t.y * t.y + t.z * t.z + t.w * t.w;
    }
#pragma unroll
    for (int o = 16; o; o >>= 1) {
        s  += __shfl_xor_sync(0xffffffffu, s, o);
        sq += __shfl_xor_sync(0xffffffffu, sq, o);
    }
    const float mu   = s * (1.f / 512.f);
    const float var  = sq * (1.f / 512.f) - mu * mu;
    const float rstd = rsqrtf(var + 1e-5f);

    float4* O4 = (float4*)(out + (size_t)row * DM);
    const float4* Ga4 = (const float4*)gamma;
    const float4* Be4 = (const float4*)beta;
#pragma unroll
    for (int j = 0; j < 4; ++j) {
        const int idx = lane + j * 32;
        float4 ga = Ga4[idx], be = Be4[idx];
        float4 o;
        o.x = nonsat_root(fmaf((h[j].x - mu) * rstd, ga.x, be.x));
        o.y = nonsat_root(fmaf((h[j].y - mu) * rstd, ga.y, be.y));
        o.z = nonsat_root(fmaf((h[j].z - mu) * rstd, ga.z, be.z));
        o.w = nonsat_root(fmaf((h[j].w - mu) * rstd, ga.w, be.w));
        O4[idx] = o;
    }
}

// ---------------------------------------------------------------------------
// Launch
// ---------------------------------------------------------------------------
extern "C" void kernel_launch(void* const* d_in, const int* in_sizes, int n_in,
                              void* d_out, int out_size) {
    (void)in_sizes; (void)n_in; (void)out_size;
    const float* x     = (const float*)d_in[0];   // (4096, 8, 512)
    const float* W     = (const float*)d_in[1];   // (512, 1024)
    const float* b     = (const float*)d_in[2];   // (512,)
    const float* gamma = (const float*)d_in[3];   // (512,)
    const float* beta  = (const float*)d_in[4];   // (512,)
    const float* pe    = (const float*)d_in[5];   // (5000, 512)
    float* out = (float*)d_out;

    cudaFuncSetAttribute(gemm_fp16_kernel,
                         cudaFuncAttributeMaxDynamicSharedMemorySize, SMEM_BYTES);

    float *G, *P;
    cudaGetSymbolAddress((void**)&G, g_G);
    cudaGetSymbolAddress((void**)&P, g_P);

    // 1) W transpose + fp16 convert
    prep_w_kernel<<<dim3(FD / 32, DM / 32), dim3(32, 32)>>>(W);
    // 2) merged GEMM launch: G = x @ W1^T  and  P = pe @ W2^T
    gemm_fp16_kernel<<<dim3(XBLOCKS + PBLOCKS, DM / BN), 256, SMEM_BYTES>>>(x, pe, G, P);
    // 3) bias + LN + low-MUFU nonsat activation
    ln_act_kernel<<<MROWS / 8, 256>>>(b, gamma, beta, out);
}

// round 16
// speedup vs baseline: 2.1700x; 1.0339x over previous
#include <cuda_runtime.h>
#include <cuda_fp16.h>
#include <cstdint>

// ---------------------------------------------------------------------------
// Problem constants
// ---------------------------------------------------------------------------
#define L_SEQ   4096
#define NBATCH  8
#define DM      512                 // d_model (output feature dim, LN dim)
#define MROWS   (L_SEQ * NBATCH)    // 32768
#define KD      512                 // K per GEMM half
#define FD      1024                // W inner dim (2*D)

// ---------------------------------------------------------------------------
// GEMM tile config  (BM=64, BN=256, BK=64)
// ---------------------------------------------------------------------------
#define BM 64
#define BN 256
#define BK 64
#define A_ROW 72                    // fp16 per A smem row (64 + 8 pad -> 144B, conflict-free)
#define W_ROW 264                   // fp16 per W smem row (256 + 8 pad -> 528B, conflict-free)
#define STG_A  (BM * A_ROW * 2)     // 9216 B
#define STG_W  (BK * W_ROW * 2)     // 33792 B
#define STAGE_BYTES (STG_A + STG_W)           // 43008  [Ah|Wh]
#define SMEM_BYTES  (2 * STAGE_BYTES)         // 86016 (double buffered)
#define NCHUNK (KD / BK)            // 8

#define XBLOCKS (MROWS / BM)        // 512
#define PBLOCKS (L_SEQ / BM)        // 64

// ---------------------------------------------------------------------------
// Device scratch (static allocation only -- no cudaMalloc allowed)
// ---------------------------------------------------------------------------
__device__ __align__(16) __half g_W1h[KD * DM];   // W[:, :512]  k-major fp16
__device__ __align__(16) __half g_W2h[KD * DM];   // W[:, 512:]  k-major fp16
__device__ __align__(16) __half g_Gh[(size_t)MROWS * DM];   // x @ W1^T  (fp16)
__device__ __align__(16) __half g_Ph[(size_t)L_SEQ * DM];   // pe @ W2^T (fp16)

// ---------------------------------------------------------------------------
// PTX helpers
// ---------------------------------------------------------------------------
__device__ __forceinline__ uint32_t smem_u32(const void* p) {
    return (uint32_t)__cvta_generic_to_shared(p);
}

__device__ __forceinline__ void ldm_x4(uint32_t* r, uint32_t addr) {
    asm volatile("ldmatrix.sync.aligned.m8n8.x4.shared.b16 {%0,%1,%2,%3}, [%4];"
                 : "=r"(r[0]), "=r"(r[1]), "=r"(r[2]), "=r"(r[3]) : "r"(addr));
}
__device__ __forceinline__ void ldm_x4_t(uint32_t* r, uint32_t addr) {
    asm volatile("ldmatrix.sync.aligned.m8n8.x4.trans.shared.b16 {%0,%1,%2,%3}, [%4];"
                 : "=r"(r[0]), "=r"(r[1]), "=r"(r[2]), "=r"(r[3]) : "r"(addr));
}
__device__ __forceinline__ void mma16816(float* c, const uint32_t* a, uint32_t b0, uint32_t b1) {
    asm volatile(
        "mma.sync.aligned.m16n8k16.row.col.f32.f16.f16.f32 "
        "{%0,%1,%2,%3},{%4,%5,%6,%7},{%8,%9},{%0,%1,%2,%3};"
        : "+f"(c[0]), "+f"(c[1]), "+f"(c[2]), "+f"(c[3])
        : "r"(a[0]), "r"(a[1]), "r"(a[2]), "r"(a[3]), "r"(b0), "r"(b1));
}
__device__ __forceinline__ void cpasync16(uint32_t dst, const void* src) {
    asm volatile("cp.async.cg.shared.global [%0], [%1], 16;" :: "r"(dst), "l"(src));
}
__device__ __forceinline__ void cp_commit() { asm volatile("cp.async.commit_group;"); }
__device__ __forceinline__ void cp_wait0()  { asm volatile("cp.async.wait_group 0;"); }

// pack a,b fp32 -> packed fp16 pair
__device__ __forceinline__ uint32_t pack_half2(float a, float b) {
    const __half2 h = __floats2half2_rn(a, b);
    return *(const uint32_t*)&h;
}

// ---------------------------------------------------------------------------
// Kernel 1: transpose + fp16 W (d,f row-major -> [f][d] k-major)
// ---------------------------------------------------------------------------
__global__ void __launch_bounds__(1024) prep_w_kernel(const float* __restrict__ W) {
    __shared__ float tile[32][33];
    const int tx = threadIdx.x, ty = threadIdx.y;
    const int f0 = blockIdx.x * 32;     // f in [0,1024)
    const int d0 = blockIdx.y * 32;     // d in [0,512)
    tile[ty][tx] = W[(size_t)(d0 + ty) * FD + (f0 + tx)];
    __syncthreads();
    const float v = tile[tx][ty];       // = W[d0+tx][f0+ty]
    const int f = f0 + ty;
    const int d = d0 + tx;
    const __half h = __float2half_rn(v);
    if (f < KD) {
        g_W1h[f * DM + d] = h;
    } else {
        g_W2h[(f - KD) * DM + d] = h;
    }
}

// ---------------------------------------------------------------------------
// Kernel 2: C[M,512] = A[M,512] @ Wt^T  single-pass fp16, fp16 output
//   blockIdx.x <  XBLOCKS : G = x  @ W1^T  -> g_Gh
//   blockIdx.x >= XBLOCKS : P = pe @ W2^T  -> g_Ph
// ---------------------------------------------------------------------------
__device__ __forceinline__ void store_a_tile(char* sb, int arow, int ac4,
                                             const float4* v) {
#pragma unroll
    for (int j = 0; j < 4; ++j) {
        const uint32_t h0 = pack_half2(v[j].x, v[j].y);
        const uint32_t h1 = pack_half2(v[j].z, v[j].w);
        const int off = (arow * A_ROW + (ac4 + 4 * j) * 4) * 2;
        *(uint2*)(sb + off) = make_uint2(h0, h1);
    }
}

__device__ __forceinline__ void cpasync_w_tile(char* sb, const __half* Wh,
                                               int k0, int n0, int tid) {
    uint32_t dh = smem_u32(sb + STG_A);
#pragma unroll
    for (int i = 0; i < 8; ++i) {
        const int id  = tid + i * 256;      // 0..2047
        const int row = id >> 5;            // 0..63  (k within chunk)
        const int c16 = id & 31;            // 16B column chunk (8 fp16)
        const uint32_t doff = (uint32_t)(row * (W_ROW * 2) + c16 * 16);
        cpasync16(dh + doff, Wh + (size_t)(k0 + row) * DM + n0 + c16 * 8);
    }
}

__global__ void __launch_bounds__(256) gemm_fp16_kernel(
    const float* __restrict__ Ax,
    const float* __restrict__ Ape,
    __half* __restrict__ Cg,
    __half* __restrict__ Cp) {
    extern __shared__ char smem[];
    const int tid    = threadIdx.x;
    const int lane   = tid & 31;
    const int wid    = tid >> 5;
    const int warp_m = wid & 1;    // 0..1
    const int warp_n = wid >> 1;   // 0..3

    // -- partition the grid between the two GEMMs --
    const float* A;
    const __half* Wh;
    __half* C;
    int m0;
    if (blockIdx.x < XBLOCKS) {
        A = Ax;  Wh = g_W1h; C = Cg;
        m0 = blockIdx.x * BM;
    } else {
        A = Ape; Wh = g_W2h; C = Cp;
        m0 = (blockIdx.x - XBLOCKS) * BM;
    }
    const int n0 = blockIdx.y * BN;

    // A global-load mapping: 64 rows x 16 float4 cols; 4 float4 per thread
    const int arow = tid >> 2;     // 0..63
    const int ac4  = tid & 3;      // 0..3
    const float* aP = A + (size_t)(m0 + arow) * KD + ac4 * 4;

    float acc[2][8][4];
#pragma unroll
    for (int i = 0; i < 2; ++i)
#pragma unroll
        for (int j = 0; j < 8; ++j)
#pragma unroll
            for (int k = 0; k < 4; ++k) acc[i][j][k] = 0.f;

    // prologue: chunk 0
    {
        float4 v[4];
#pragma unroll
        for (int j = 0; j < 4; ++j) v[j] = *(const float4*)(aP + j * 16);
        store_a_tile(smem, arow, ac4, v);
        cpasync_w_tile(smem, Wh, 0, n0, tid);
        cp_commit();
    }

    // per-lane ldmatrix address components (constant across chunks)
    const int a_r  = (lane & 7) + ((lane >> 3) & 1) * 8;  // row within 16-tile
    const int a_k8 = (lane >> 4) * 8;                     // 8-elem k chunk
    const int w_k  = (lane & 7) + ((lane >> 3) & 1) * 8;  // k row within 16
    const int w_n8 = (lane >> 4) * 8;                     // 8-elem n chunk

    for (int ch = 0; ch < NCHUNK; ++ch) {
        const int cur  = ch & 1;
        const bool more = (ch + 1) < NCHUNK;
        float4 na[4];
        if (more) {
#pragma unroll
            for (int j = 0; j < 4; ++j)
                na[j] = *(const float4*)(aP + (ch + 1) * BK + j * 16);
        }
        cp_wait0();
        __syncthreads();
        if (more) {
            cpasync_w_tile(smem + (cur ^ 1) * STAGE_BYTES, Wh,
                           (ch + 1) * BK, n0, tid);
            cp_commit();
        }
        // ---- compute on stage `cur` ----
        char* sb = smem + cur * STAGE_BYTES;
        const uint32_t sAh = smem_u32(sb);
        const uint32_t sWh = sAh + STG_A;
#pragma unroll
        for (int ks = 0; ks < 4; ++ks) {
            uint32_t af[2][4];
#pragma unroll
            for (int mt = 0; mt < 2; ++mt) {
                const int row  = warp_m * 32 + mt * 16 + a_r;
                const int koff = ks * 16 + a_k8;
                ldm_x4(af[mt], sAh + (uint32_t)(row * A_ROW + koff) * 2);
            }
#pragma unroll
            for (int nt2 = 0; nt2 < 4; ++nt2) {
                const int krow = ks * 16 + w_k;
                const int ncol = warp_n * 64 + nt2 * 16 + w_n8;
                uint32_t w[4];
                ldm_x4_t(w, sWh + (uint32_t)(krow * W_ROW + ncol) * 2);
#pragma unroll
                for (int mt = 0; mt < 2; ++mt) {
                    mma16816(acc[mt][nt2 * 2],     af[mt], w[0], w[1]);
                    mma16816(acc[mt][nt2 * 2 + 1], af[mt], w[2], w[3]);
                }
            }
        }
        if (more) {
            store_a_tile(smem + (cur ^ 1) * STAGE_BYTES, arow, ac4, na);
        }
    }

    // ---- epilogue: write fp16 tile (half traffic of fp32) ----
#pragma unroll
    for (int mt = 0; mt < 2; ++mt) {
        const int r0 = m0 + warp_m * 32 + mt * 16 + (lane >> 2);
#pragma unroll
        for (int n8 = 0; n8 < 8; ++n8) {
            const int cb = n0 + warp_n * 64 + n8 * 8 + (lane & 3) * 2;
            *(uint32_t*)(C + (size_t)r0 * DM + cb) =
                pack_half2(acc[mt][n8][0], acc[mt][n8][1]);
            *(uint32_t*)(C + (size_t)(r0 + 8) * DM + cb) =
                pack_half2(acc[mt][n8][2], acc[mt][n8][3]);
        }
    }
}

// ---------------------------------------------------------------------------
// nonsat activation: exact root of  y + y^3/3 = z
// y = q^{1/3} - q^{-1/3} with q = 1.5z + sqrt((1.5z)^2+1); v = q^{-1/3} by
// bit-trick seed + 3 division-free Newton steps; 1 fast-div polish.
// MUFU ops: 1 RSQ + 1 RCP.
// ---------------------------------------------------------------------------
__device__ __forceinline__ float nonsat_root(float z) {
    const float s = 1.5f * fabsf(z);
    const float w = fmaf(s, s, 1.0f);
    const float t = w * rsqrtf(w);               // sqrt(w), 1 MUFU
    const float q = s + t;                       // q >= 1
    float v = __int_as_float(0x549E80CE - __float_as_int(q) / 3);
#pragma unroll
    for (int it = 0; it < 3; ++it) {
        const float vv = v * v;
        v = v * fmaf(-q * v, vv, 4.0f) * (1.0f / 3.0f);
    }
    float y = fmaf(q * v, v, -v);                // u - 1/u
    y = copysignf(y, z);
    const float yy = y * y;
    y = __fdividef(fmaf(0.66666666666667f * yy, y, z), yy + 1.0f);
    return y;
}

// ---------------------------------------------------------------------------
// Kernel 3: h = G + P + b ; LayerNorm(gamma,beta) ; nonsat activation
// one warp per row (512 cols). G,P read as fp16 (half the traffic).
// ---------------------------------------------------------------------------
__global__ void __launch_bounds__(256) ln_act_kernel(
    const float* __restrict__ bias, const float* __restrict__ gamma,
    const float* __restrict__ beta, float* __restrict__ out) {
    const int row  = (int)((blockIdx.x * 256 + threadIdx.x) >> 5);
    const int lane = threadIdx.x & 31;

    const uint4* G4 = (const uint4*)(g_Gh + (size_t)row * DM);       // 8 halves per uint4
    const uint4* P4 = (const uint4*)(g_Ph + (size_t)(row >> 3) * DM);
    const float4* B4 = (const float4*)bias;

    float h[2][8];
    float s = 0.f, sq = 0.f;
#pragma unroll
    for (int j = 0; j < 2; ++j) {
        const int idx = lane + j * 32;          // uint4 index, 0..63
        const uint4 gv = G4[idx];
        const uint4 pv = P4[idx];
        const float4 b0 = B4[idx * 2], b1 = B4[idx * 2 + 1];
        const float2 g0 = __half22float2(*(const __half2*)&gv.x);
        const float2 g1 = __half22float2(*(const __half2*)&gv.y);
        const float2 g2 = __half22float2(*(const __half2*)&gv.z);
        const float2 g3 = __half22float2(*(const __half2*)&gv.w);
        const float2 p0 = __half22float2(*(const __half2*)&pv.x);
        const float2 p1 = __half22float2(*(const __half2*)&pv.y);
        const float2 p2 = __half22float2(*(const __half2*)&pv.z);
        const float2 p3 = __half22float2(*(const __half2*)&pv.w);
        h[j][0] = g0.x + p0.x + b0.x;
        h[j][1] = g0.y + p0.y + b0.y;
        h[j][2] = g1.x + p1.x + b0.z;
        h[j][3] = g1.y + p1.y + b0.w;
        h[j][4] = g2.x + p2.x + b1.x;
        h[j][5] = g2.y + p2.y + b1.y;
        h[j][6] = g3.x + p3.x + b1.z;
        h[j][7] = g3.y + p3.y + b1.w;
#pragma unroll
        for (int c = 0; c < 8; ++c) {
            s  += h[j][c];
            sq += h[j][c] * h[j][c];
        }
    }
#pragma unroll
    for (int o = 16; o; o >>= 1) {
        s  += __shfl_xor_sync(0xffffffffu, s, o);
        sq += __shfl_xor_sync(0xffffffffu, sq, o);
    }
    const float mu   = s * (1.f / 512.f);
    const float var  = sq * (1.f / 512.f) - mu * mu;
    const float rstd = rsqrtf(var + 1e-5f);

    float4* O4 = (float4*)(out + (size_t)row * DM);
    const float4* Ga4 = (const float4*)gamma;
    const float4* Be4 = (const float4*)beta;
#pragma unroll
    for (int j = 0; j < 2; ++j) {
        const int idx = lane + j * 32;
        const float4 ga0 = Ga4[idx * 2], ga1 = Ga4[idx * 2 + 1];
        const float4 be0 = Be4[idx * 2], be1 = Be4[idx * 2 + 1];
        float4 o0, o1;
        o0.x = nonsat_root(fmaf((h[j][0] - mu) * rstd, ga0.x, be0.x));
        o0.y = nonsat_root(fmaf((h[j][1] - mu) * rstd, ga0.y, be0.y));
        o0.z = nonsat_root(fmaf((h[j][2] - mu) * rstd, ga0.z, be0.z));
        o0.w = nonsat_root(fmaf((h[j][3] - mu) * rstd, ga0.w, be0.w));
        o1.x = nonsat_root(fmaf((h[j][4] - mu) * rstd, ga1.x, be1.x));
        o1.y = nonsat_root(fmaf((h[j][5] - mu) * rstd, ga1.y, be1.y));
        o1.z = nonsat_root(fmaf((h[j][6] - mu) * rstd, ga1.z, be1.z));
        o1.w = nonsat_root(fmaf((h[j][7] - mu) * rstd, ga1.w, be1.w));
        O4[idx * 2]     = o0;
        O4[idx * 2 + 1] = o1;
    }
}

// ---------------------------------------------------------------------------
// Launch
// ---------------------------------------------------------------------------
extern "C" void kernel_launch(void* const* d_in, const int* in_sizes, int n_in,
                              void* d_out, int out_size) {
    (void)in_sizes; (void)n_in; (void)out_size;
    const float* x     = (const float*)d_in[0];   // (4096, 8, 512)
    const float* W     = (const float*)d_in[1];   // (512, 1024)
    const float* b     = (const float*)d_in[2];   // (512,)
    const float* gamma = (const float*)d_in[3];   // (512,)
    const float* beta  = (const float*)d_in[4];   // (512,)
    const float* pe    = (const float*)d_in[5];   // (5000, 512)
    float* out = (float*)d_out;

    cudaFuncSetAttribute(gemm_fp16_kernel,
                         cudaFuncAttributeMaxDynamicSharedMemorySize, SMEM_BYTES);

    __half *G, *P;
    cudaGetSymbolAddress((void**)&G, g_Gh);
    cudaGetSymbolAddress((void**)&P, g_Ph);

    // 1) W transpose + fp16 convert
    prep_w_kernel<<<dim3(FD / 32, DM / 32), dim3(32, 32)>>>(W);
    // 2) merged GEMM launch: G = x @ W1^T  and  P = pe @ W2^T  (fp16 out)
    gemm_fp16_kernel<<<dim3(XBLOCKS + PBLOCKS, DM / BN), 256, SMEM_BYTES>>>(x, pe, G, P);
    // 3) bias + LN + low-MUFU nonsat activation
    ln_act_kernel<<<MROWS / 8, 256>>>(b, gamma, beta, out);
}